// round 3
// baseline (speedup 1.0000x reference)
#include <cuda_runtime.h>

// ---------------------------------------------------------------------------
// Problem constants
//   x[8192,512], kg[200000,64], idx/mask[8192,50]
//   Wkg[64,64], W1a[512,128], W1b[128,512], W1c[512,128], W1d[128,64], W2[64,1024]
//   out[8192,1024] fp32
// ---------------------------------------------------------------------------

// Scratch (allocation-free: __device__ globals)
__device__ float g_h1[8192 * 128];
__device__ float g_h2[8192 * 512];
__device__ float g_h3[8192 * 128];
__device__ float g_know[8192 * 64];
__device__ float g_h[8192 * 64];

// ---------------------------------------------------------------------------
// Knowledge branch: out[b,c] = sum_k mask[b,k] * relu( kg[idx[b,k],:] @ Wkg[:,c] + bkg[c] )
// One warp per b. Lane computes columns (lane, lane+32) via paired float2 weights.
// idx/mask are distributed across lanes (lane l holds k=l, k=l+32) and
// broadcast with __shfl_sync — no scalar LDG in the hot loop.
// ---------------------------------------------------------------------------
__global__ __launch_bounds__(256)
void knowledge_kernel(const float* __restrict__ kg, const int* __restrict__ idx,
                      const int* __restrict__ mask, const float* __restrict__ Wkg,
                      const float* __restrict__ bkg, float* __restrict__ out) {
    __shared__ float2 wk2[64][32];      // wk2[d][c] = (Wkg[d][c], Wkg[d][c+32])
    __shared__ float2 bk2[32];
    __shared__ float  rowbuf[8][68];    // per-warp gathered row (pad keeps 16B align)

    const int tid = threadIdx.x;
    for (int i = tid; i < 64 * 32; i += 256) {
        int d = i >> 5, c = i & 31;
        wk2[d][c] = make_float2(Wkg[d * 64 + c], Wkg[d * 64 + c + 32]);
    }
    if (tid < 32) bk2[tid] = make_float2(bkg[tid], bkg[tid + 32]);
    __syncthreads();

    const int warp = tid >> 5, lane = tid & 31;
    const int b = blockIdx.x * 8 + warp;
    float* rb = rowbuf[warp];

    // Distribute idx/mask over lanes: lane l holds k=l and (if l<18) k=l+32.
    int my_i0 = __ldg(idx  + (size_t)b * 50 + lane);
    int my_m0 = __ldg(mask + (size_t)b * 50 + lane);
    int my_i1 = 0, my_m1 = 0;
    if (lane < 18) {
        my_i1 = __ldg(idx  + (size_t)b * 50 + 32 + lane);
        my_m1 = __ldg(mask + (size_t)b * 50 + 32 + lane);
    }

    float s0 = 0.f, s1 = 0.f;
    const float bb0 = bk2[lane].x, bb1 = bk2[lane].y;

    #pragma unroll 2
    for (int k = 0; k < 50; k++) {
        int src = k & 31;
        int m = __shfl_sync(0xffffffffu, (k < 32) ? my_m0 : my_m1, src);
        if (m) {                                         // warp-uniform branch
            int r = __shfl_sync(0xffffffffu, (k < 32) ? my_i0 : my_i1, src);
            float2 v = *(const float2*)(kg + (size_t)r * 64 + lane * 2);
            __syncwarp();
            *(float2*)&rb[lane * 2] = v;
            __syncwarp();
            float a0 = bb0, a1 = bb1;
            #pragma unroll
            for (int d4 = 0; d4 < 16; d4++) {
                float4 rv = *(const float4*)&rb[d4 * 4];
                float rr[4] = {rv.x, rv.y, rv.z, rv.w};
                #pragma unroll
                for (int q = 0; q < 4; q++) {
                    float2 w = wk2[d4 * 4 + q][lane];
                    a0 = fmaf(rr[q], w.x, a0);
                    a1 = fmaf(rr[q], w.y, a1);
                }
            }
            s0 += fmaxf(a0, 0.f);
            s1 += fmaxf(a1, 0.f);
        }
    }
    out[(size_t)b * 64 + lane]      = s0;
    out[(size_t)b * 64 + lane + 32] = s1;
}

// ---------------------------------------------------------------------------
// Tiled SGEMM: C[M,N] = act(A[M,K] @ W[K,N] + bias) (+ X when ADDX)
// BM=64, BN=64, BK=32, 256 threads, 4x4 microtile per thread.
//   As[m][k] stride 36 (phase-conflict-free float4 stores, contiguous k frags)
//   Bs[k][n] stride 64
// All dims here divide the tile sizes (M=8192; N in {64,128,512,1024}; K in {64,128,512}).
// ---------------------------------------------------------------------------
template<bool RELU, bool ADDX>
__global__ __launch_bounds__(256)
void sgemm_kernel(const float* __restrict__ A, const float* __restrict__ W,
                  const float* __restrict__ bias, const float* __restrict__ X,
                  float* __restrict__ C, int M, int K, int N) {
    __shared__ float As[64][36];
    __shared__ float Bs[32][64];

    const int tid = threadIdx.x;
    const int tc = tid & 15;            // output col group (tc*4)
    const int tr = tid >> 4;            // output row group (tr*4)
    const int m0 = blockIdx.x * 64;
    const int n0 = blockIdx.y * 64;

    const int a_row = tid >> 3;         // 0..31 (and +32)
    const int a_col = (tid & 7) << 2;   // 0..28
    const int b_row = tid >> 4;         // 0..15 (and +16)
    const int b_col = (tid & 15) << 2;  // 0..60

    const float* Ap0 = A + (size_t)(m0 + a_row) * K + a_col;
    const float* Ap1 = Ap0 + (size_t)32 * K;
    const float* Wp0 = W + (size_t)b_row * N + n0 + b_col;
    const float* Wp1 = Wp0 + (size_t)16 * N;

    float acc[4][4] = {};

    for (int k0 = 0; k0 < K; k0 += 32) {
        float4 av0 = *(const float4*)(Ap0 + k0);
        float4 av1 = *(const float4*)(Ap1 + k0);
        float4 bv0 = *(const float4*)(Wp0 + (size_t)k0 * N);
        float4 bv1 = *(const float4*)(Wp1 + (size_t)k0 * N);
        __syncthreads();
        *(float4*)&As[a_row][a_col]      = av0;
        *(float4*)&As[a_row + 32][a_col] = av1;
        *(float4*)&Bs[b_row][b_col]      = bv0;
        *(float4*)&Bs[b_row + 16][b_col] = bv1;
        __syncthreads();

        #pragma unroll
        for (int kk = 0; kk < 32; kk += 4) {
            float a[4][4], bfr[4][4];
            #pragma unroll
            for (int i = 0; i < 4; i++) {
                float4 t = *(const float4*)&As[tr * 4 + i][kk];
                a[i][0] = t.x; a[i][1] = t.y; a[i][2] = t.z; a[i][3] = t.w;
            }
            #pragma unroll
            for (int dk = 0; dk < 4; dk++) {
                float4 t = *(const float4*)&Bs[kk + dk][tc * 4];
                bfr[dk][0] = t.x; bfr[dk][1] = t.y; bfr[dk][2] = t.z; bfr[dk][3] = t.w;
            }
            #pragma unroll
            for (int i = 0; i < 4; i++)
                #pragma unroll
                for (int dk = 0; dk < 4; dk++)
                    #pragma unroll
                    for (int j = 0; j < 4; j++)
                        acc[i][j] = fmaf(a[i][dk], bfr[dk][j], acc[i][j]);
        }
    }

    // Epilogue: bias (+relu) (+X), float4 stores
    #pragma unroll
    for (int i = 0; i < 4; i++) {
        const int m = m0 + tr * 4 + i;
        float o[4];
        #pragma unroll
        for (int j = 0; j < 4; j++) {
            const int n = n0 + tc * 4 + j;
            float v = acc[i][j] + bias[n];
            if (RELU) v = fmaxf(v, 0.f);
            if (ADDX) v += X[(size_t)m * N + n];
            o[j] = v;
        }
        *(float4*)(C + (size_t)m * N + n0 + tc * 4) = *(float4*)o;
    }
}

// ---------------------------------------------------------------------------
// Launch
// ---------------------------------------------------------------------------
extern "C" void kernel_launch(void* const* d_in, const int* in_sizes, int n_in,
                              void* d_out, int out_size) {
    const float* x    = (const float*)d_in[0];
    const float* kg   = (const float*)d_in[1];
    const int*   idx  = (const int*)  d_in[2];
    const int*   mask = (const int*)  d_in[3];
    const float* Wkg  = (const float*)d_in[4];
    const float* bkg  = (const float*)d_in[5];
    const float* W1a  = (const float*)d_in[6];
    const float* b1a  = (const float*)d_in[7];
    const float* W1b  = (const float*)d_in[8];
    const float* b1b  = (const float*)d_in[9];
    const float* W1c  = (const float*)d_in[10];
    const float* b1c  = (const float*)d_in[11];
    const float* W1d  = (const float*)d_in[12];
    const float* b1d  = (const float*)d_in[13];
    const float* W2   = (const float*)d_in[14];
    const float* b2   = (const float*)d_in[15];
    float* out = (float*)d_out;

    float *h1, *h2, *h3, *know, *h;
    cudaGetSymbolAddress((void**)&h1,   g_h1);
    cudaGetSymbolAddress((void**)&h2,   g_h2);
    cudaGetSymbolAddress((void**)&h3,   g_h3);
    cudaGetSymbolAddress((void**)&know, g_know);
    cudaGetSymbolAddress((void**)&h,    g_h);

    const int M = 8192;

    // Knowledge branch (independent of MLP chain)
    knowledge_kernel<<<M / 8, 256>>>(kg, idx, mask, Wkg, bkg, know);

    // Dense MLP chain
    sgemm_kernel<true,  false><<<dim3(M / 64, 2),  256>>>(x,  W1a, b1a, nullptr, h1, M, 512, 128);
    sgemm_kernel<true,  false><<<dim3(M / 64, 8),  256>>>(h1, W1b, b1b, nullptr, h2, M, 128, 512);
    sgemm_kernel<true,  false><<<dim3(M / 64, 2),  256>>>(h2, W1c, b1c, nullptr, h3, M, 512, 128);
    // h = relu(h3 @ W1d + b1d) + knowledge
    sgemm_kernel<true,  true ><<<dim3(M / 64, 1),  256>>>(h3, W1d, b1d, know,    h,  M, 128, 64);
    // out = h @ W2 + b2
    sgemm_kernel<false, false><<<dim3(M / 64, 16), 256>>>(h,  W2,  b2,  nullptr, out, M, 64, 1024);
}